// round 14
// baseline (speedup 1.0000x reference)
#include <cuda_runtime.h>
#include <math.h>

#define NN 100000
#define DD 128
#define CC 40
#define EPSBN 1e-5f
#define EMAX 1000000   // 600000 edges + <=3 pad per node
#define NBLK_SCAN 391  // 391*256 >= NN

// ---- scratch (device globals) ----
__device__ float4 g_hw4[NN * 32];     // h @ W (gemm output)
__device__ float4 g_agg4[NN * 32];    // aggregated
__device__ float  g_dinv[NN];
__device__ int    g_degi[NN];         // zeroed at end of each replay (scanA)
__device__ int    g_rowptr[NN + 1];   // padded-CSR row starts (multiples of 4)
__device__ int    g_cursor[NN];
__device__ int    g_csrsrc[EMAX];
__device__ float  g_csrw[EMAX];
__device__ float  g_stats[3][256];    // per layer: [0:128)=colsum, [128:256)=colsumsq
__device__ int    g_bsum[NBLK_SCAN];
__device__ int    g_boff[NBLK_SCAN];

#define FMA2(acc, a, b) \
    asm("fma.rn.f32x2 %0, %1, %2, %0;" : "+l"(acc) : "l"(a), "l"(b))

// ---------------- degree count ----------------
__global__ void deg_count_k(const int* __restrict__ dst, int E) {
    int e = blockIdx.x * blockDim.x + threadIdx.x;
    if (e < E) atomicAdd(&g_degi[dst[e]], 1);
}

// ---------------- hierarchical scan over padded degrees ----------------
__global__ __launch_bounds__(256) void scanA_k() {
    __shared__ int sm[256];
    int t = threadIdx.x;
    int i = blockIdx.x * 256 + t;
    int d = 0;
    if (i < NN) {
        d = g_degi[i];
        g_degi[i] = 0;                         // ready for next replay
        g_dinv[i] = rsqrtf((float)(d + 1));    // +1 = self-loop
    }
    int p = (d + 3) & ~3;
    sm[t] = p;
    __syncthreads();
#pragma unroll
    for (int off = 1; off < 256; off <<= 1) {
        int v = (t >= off) ? sm[t - off] : 0;
        __syncthreads();
        sm[t] += v;
        __syncthreads();
    }
    if (i < NN) g_rowptr[i] = sm[t] - p;       // exclusive within block
    if (t == 255) g_bsum[blockIdx.x] = sm[255];
}

__global__ void scanB_k() {
    __shared__ int sm[512];
    int t = threadIdx.x;
    int v = (t < NBLK_SCAN) ? g_bsum[t] : 0;
    sm[t] = v;
    __syncthreads();
#pragma unroll
    for (int off = 1; off < 512; off <<= 1) {
        int u = (t >= off) ? sm[t - off] : 0;
        __syncthreads();
        sm[t] += u;
        __syncthreads();
    }
    if (t < NBLK_SCAN) g_boff[t] = sm[t] - v;
    if (t == NBLK_SCAN - 1) g_rowptr[NN] = sm[t];
}

__global__ __launch_bounds__(256) void scanC_k() {
    int i = blockIdx.x * 256 + threadIdx.x;
    if (i >= NN) return;
    int v = g_rowptr[i] + g_boff[blockIdx.x];
    g_rowptr[i] = v;
    g_cursor[i] = v;
}

__global__ void fill_k(const int* __restrict__ src, const int* __restrict__ dst, int E) {
    int e = blockIdx.x * blockDim.x + threadIdx.x;
    if (e >= E) return;
    int s = src[e], d = dst[e];
    int pos = atomicAdd(&g_cursor[d], 1);
    g_csrsrc[pos] = s;
    g_csrw[pos] = g_dinv[s] * g_dinv[d];
}

__global__ void pad_k() {
    int i = blockIdx.x * blockDim.x + threadIdx.x;
    if (i >= NN) return;
    int j = g_cursor[i], end = g_rowptr[i + 1];
    for (; j < end; j++) { g_csrsrc[j] = i; g_csrw[j] = 0.f; }
}

// ---------------- fused GEMM: 64x128 tile, 256 thr, 4x8 microtile, 2 blocks/SM ----------------
// C[n,128] = f(A)[n,128] @ B[128,128] (+bias)(+relu)
// cols split: chunk tx (cols 4tx..) and chunk tx+16 (cols 64+4tx..) -- conflict-free B LDS
__global__ __launch_bounds__(256, 2) void gemm128_k(
    const float4* __restrict__ A4, const float* __restrict__ B,
    const float* __restrict__ bias, float* __restrict__ Cout,
    int n, int bnl, int relu, int zstat,
    const float* __restrict__ gammas, const float* __restrict__ betas,
    const float* __restrict__ pa, float4* __restrict__ hout4)
{
    extern __shared__ float smf[];
    float4* As4 = (float4*)smf;                 // [64 rows][32 chunks] = 32KB
    float4* Bs4 = (float4*)(smf + 64 * DD);     // [128 k][32 chunks] = 64KB
    __shared__ float s_scale[DD];
    __shared__ float s_shift[DD];
    int tid = threadIdx.x;
    int r0 = blockIdx.x * 64;

    if (zstat >= 0) ((float*)g_stats)[zstat * 256 + tid] = 0.f;

    float slope = 0.f;
    if (bnl >= 0) {
        slope = __ldg(&pa[bnl]);
        if (tid < DD) {
            float su = g_stats[bnl][tid];
            float sq = g_stats[bnl][tid + 128];
            const float invN = 1.0f / NN;
            float mu = su * invN;
            float var = sq * invN - mu * mu;
            float rs = rsqrtf(var + EPSBN);
            float g = __ldg(&gammas[bnl * DD + tid]);
            float sc = rs * g;
            s_scale[tid] = sc;
            s_shift[tid] = __ldg(&betas[bnl * DD + tid]) - mu * sc;
        }
    }

    // load B: 4096 float4 / 256 thr = 16 each
    {
        const float4* B4 = (const float4*)B;
#pragma unroll
        for (int i = 0; i < 16; i++) Bs4[tid + i * 256] = B4[tid + i * 256];
    }
    if (bnl >= 0) __syncthreads();   // s_scale ready before A transform

    // load + transform A tile: 2048 float4 / 256 thr = 8 each
#pragma unroll
    for (int i = 0; i < 8; i++) {
        int j = tid + i * 256;
        int r = j >> 5, c4 = j & 31;
        float4 v = make_float4(0.f, 0.f, 0.f, 0.f);
        if (r0 + r < n) {
            v = A4[(size_t)(r0 + r) * 32 + c4];
            if (bnl >= 0) {
                float4 sc = ((const float4*)s_scale)[c4];
                float4 sh = ((const float4*)s_shift)[c4];
                float h;
                h = v.x * sc.x + sh.x;  v.x = h > 0.f ? h : slope * h;
                h = v.y * sc.y + sh.y;  v.y = h > 0.f ? h : slope * h;
                h = v.z * sc.z + sh.z;  v.z = h > 0.f ? h : slope * h;
                h = v.w * sc.w + sh.w;  v.w = h > 0.f ? h : slope * h;
            }
            if (hout4) hout4[(size_t)(r0 + r) * 32 + c4] = v;
        }
        As4[j] = v;
    }
    __syncthreads();

    int ty = tid >> 4;      // 0..15 -> rows ty*4 .. ty*4+3
    int tx = tid & 15;      // chunk tx (cols 4tx..4tx+3) and chunk tx+16 (cols 64+4tx..)

    const ulonglong2* Bu = (const ulonglong2*)Bs4;

    // acc[i][0,1] = chunk tx; acc[i][2,3] = chunk tx+16
    unsigned long long acc[4][4];
#pragma unroll
    for (int i = 0; i < 4; i++)
#pragma unroll
        for (int j = 0; j < 4; j++) acc[i][j] = 0ULL;

#pragma unroll 2
    for (int k0 = 0; k0 < DD; k0 += 4) {
        float4 a4[4];
#pragma unroll
        for (int i = 0; i < 4; i++)
            a4[i] = As4[(ty * 4 + i) * 32 + (k0 >> 2)];
#pragma unroll
        for (int kk = 0; kk < 4; kk++) {
            ulonglong2 b0 = Bu[(k0 + kk) * 32 + tx];        // cols 4tx..4tx+3
            ulonglong2 b1 = Bu[(k0 + kk) * 32 + 16 + tx];   // cols 64+4tx..
#pragma unroll
            for (int i = 0; i < 4; i++) {
                float av = ((const float*)&a4[i])[kk];
                unsigned long long ap;
                asm("mov.b64 %0, {%1, %1};" : "=l"(ap) : "f"(av));
                FMA2(acc[i][0], ap, b0.x);
                FMA2(acc[i][1], ap, b0.y);
                FMA2(acc[i][2], ap, b1.x);
                FMA2(acc[i][3], ap, b1.y);
            }
        }
    }

    float bias0[4], bias1[4];
#pragma unroll
    for (int j = 0; j < 4; j++) {
        bias0[j] = bias ? __ldg(&bias[tx * 4 + j]) : 0.f;
        bias1[j] = bias ? __ldg(&bias[64 + tx * 4 + j]) : 0.f;
    }

#pragma unroll
    for (int i = 0; i < 4; i++) {
        int r = r0 + ty * 4 + i;
        if (r < n) {
            float c0, c1, c2, c3, c4f, c5, c6, c7;
            asm("mov.b64 {%0, %1}, %2;" : "=f"(c0), "=f"(c1) : "l"(acc[i][0]));
            asm("mov.b64 {%0, %1}, %2;" : "=f"(c2), "=f"(c3) : "l"(acc[i][1]));
            asm("mov.b64 {%0, %1}, %2;" : "=f"(c4f), "=f"(c5) : "l"(acc[i][2]));
            asm("mov.b64 {%0, %1}, %2;" : "=f"(c6), "=f"(c7) : "l"(acc[i][3]));
            float4 o0 = make_float4(c0 + bias0[0], c1 + bias0[1], c2 + bias0[2], c3 + bias0[3]);
            float4 o1 = make_float4(c4f + bias1[0], c5 + bias1[1], c6 + bias1[2], c7 + bias1[3]);
            if (relu) {
                o0.x = fmaxf(o0.x, 0.f); o0.y = fmaxf(o0.y, 0.f);
                o0.z = fmaxf(o0.z, 0.f); o0.w = fmaxf(o0.w, 0.f);
                o1.x = fmaxf(o1.x, 0.f); o1.y = fmaxf(o1.y, 0.f);
                o1.z = fmaxf(o1.z, 0.f); o1.w = fmaxf(o1.w, 0.f);
            }
            float4* Cr = (float4*)(Cout + (size_t)r * DD);
            Cr[tx]      = o0;
            Cr[16 + tx] = o1;
        }
    }
}

// ---------------- CSR aggregation (padded, 8-wide MLP, meta prefetch) + BN stats ----------------
__global__ __launch_bounds__(256) void csr_agg_k(const float4* __restrict__ hw,
                                                 float4* __restrict__ agg, int l)
{
    __shared__ float s_part[8][256];
    int tid = threadIdx.x, w = tid >> 5, lane = tid & 31;
    float4 rs = make_float4(0.f, 0.f, 0.f, 0.f);
    float4 rq = make_float4(0.f, 0.f, 0.f, 0.f);
    int nw = gridDim.x * 8;
    int i = blockIdx.x * 8 + w;

    int rp0 = 0, rp1 = 0;
    float di = 0.f;
    if (i < NN) {
        rp0 = g_rowptr[i];
        rp1 = g_rowptr[i + 1];
        di  = g_dinv[i];
    }

    while (i < NN) {
        int inext = i + nw;
        int np0 = 0, np1 = 0;
        float ndi = 0.f;
        if (inext < NN) {
            np0 = g_rowptr[inext];
            np1 = g_rowptr[inext + 1];
            ndi = g_dinv[inext];
        }

        float sw = di * di;
        float4 v = hw[(size_t)i * 32 + lane];
        v.x *= sw; v.y *= sw; v.z *= sw; v.w *= sw;
        int j = rp0, end = rp1;
        for (; j + 8 <= end; j += 8) {
            int4   sa = *(const int4*)(g_csrsrc + j);
            int4   sb = *(const int4*)(g_csrsrc + j + 4);
            float4 wa = *(const float4*)(g_csrw + j);
            float4 wb = *(const float4*)(g_csrw + j + 4);
            float4 u0 = hw[(size_t)sa.x * 32 + lane];
            float4 u1 = hw[(size_t)sa.y * 32 + lane];
            float4 u2 = hw[(size_t)sa.z * 32 + lane];
            float4 u3 = hw[(size_t)sa.w * 32 + lane];
            float4 u4 = hw[(size_t)sb.x * 32 + lane];
            float4 u5 = hw[(size_t)sb.y * 32 + lane];
            float4 u6 = hw[(size_t)sb.z * 32 + lane];
            float4 u7 = hw[(size_t)sb.w * 32 + lane];
            v.x += wa.x * u0.x + wa.y * u1.x + wa.z * u2.x + wa.w * u3.x
                 + wb.x * u4.x + wb.y * u5.x + wb.z * u6.x + wb.w * u7.x;
            v.y += wa.x * u0.y + wa.y * u1.y + wa.z * u2.y + wa.w * u3.y
                 + wb.x * u4.y + wb.y * u5.y + wb.z * u6.y + wb.w * u7.y;
            v.z += wa.x * u0.z + wa.y * u1.z + wa.z * u2.z + wa.w * u3.z
                 + wb.x * u4.z + wb.y * u5.z + wb.z * u6.z + wb.w * u7.z;
            v.w += wa.x * u0.w + wa.y * u1.w + wa.z * u2.w + wa.w * u3.w
                 + wb.x * u4.w + wb.y * u5.w + wb.z * u6.w + wb.w * u7.w;
        }
        if (j < end) {
            int4   s4 = *(const int4*)(g_csrsrc + j);
            float4 w4 = *(const float4*)(g_csrw + j);
            float4 u0 = hw[(size_t)s4.x * 32 + lane];
            float4 u1 = hw[(size_t)s4.y * 32 + lane];
            float4 u2 = hw[(size_t)s4.z * 32 + lane];
            float4 u3 = hw[(size_t)s4.w * 32 + lane];
            v.x += w4.x * u0.x + w4.y * u1.x + w4.z * u2.x + w4.w * u3.x;
            v.y += w4.x * u0.y + w4.y * u1.y + w4.z * u2.y + w4.w * u3.y;
            v.z += w4.x * u0.z + w4.y * u1.z + w4.z * u2.z + w4.w * u3.z;
            v.w += w4.x * u0.w + w4.y * u1.w + w4.z * u2.w + w4.w * u3.w;
        }
        agg[(size_t)i * 32 + lane] = v;
        rs.x += v.x; rs.y += v.y; rs.z += v.z; rs.w += v.w;
        rq.x += v.x * v.x; rq.y += v.y * v.y; rq.z += v.z * v.z; rq.w += v.w * v.w;

        i = inext; rp0 = np0; rp1 = np1; di = ndi;
    }
    ((float4*)&s_part[w][0])[lane] = rs;
    ((float4*)&s_part[w][128])[lane] = rq;
    __syncthreads();
    float a = 0.f;
#pragma unroll
    for (int w2 = 0; w2 < 8; w2++) a += s_part[w2][tid];
    atomicAdd(&((float*)g_stats)[l * 256 + tid], a);
}

// ---------------- head: logits = T @ Wh2 + bh2, argmax (first-index ties) ----------------
__global__ __launch_bounds__(256) void head2_k(const float4* __restrict__ T4,
                                               const float* __restrict__ Wh2,
                                               const float* __restrict__ bh2,
                                               float* __restrict__ logits,
                                               float* __restrict__ amax)
{
    __shared__ float4 Wt[CC][32];   // [col][chunk], XOR swizzled
    __shared__ float bsh[CC];
    int tid = threadIdx.x;
    for (int idx = tid; idx < CC * 32; idx += 256) {
        int c = idx >> 5, q = idx & 31;
        int k = q * 4;
        float4 v = make_float4(Wh2[k * CC + c], Wh2[(k + 1) * CC + c],
                               Wh2[(k + 2) * CC + c], Wh2[(k + 3) * CC + c]);
        Wt[c][q ^ (c & 31)] = v;
    }
    if (tid < CC) bsh[tid] = bh2[tid];
    __syncthreads();

    int w = tid >> 5, lane = tid & 31;
    __shared__ float4 rows[8][32];
    for (int r = blockIdx.x * 8 + w; r < NN; r += gridDim.x * 8) {
        rows[w][lane] = T4[(size_t)r * 32 + lane];
        __syncwarp();

        bool has2 = lane < 8;
        float acc0 = bsh[lane];
        float acc1 = has2 ? bsh[32 + lane] : -1e30f;
#pragma unroll 8
        for (int q = 0; q < 32; q++) {
            float4 rv = rows[w][q];
            float4 w0 = Wt[lane][q ^ lane];
            acc0 += rv.x * w0.x + rv.y * w0.y + rv.z * w0.z + rv.w * w0.w;
            if (has2) {
                float4 w1 = Wt[32 + lane][q ^ lane];
                acc1 += rv.x * w1.x + rv.y * w1.y + rv.z * w1.z + rv.w * w1.w;
            }
        }
        logits[(size_t)r * CC + lane] = acc0;
        if (has2) logits[(size_t)r * CC + 32 + lane] = acc1;

        float bv = acc0; int bi = lane;
        if (has2 && acc1 > bv) { bv = acc1; bi = 32 + lane; }
#pragma unroll
        for (int off = 16; off > 0; off >>= 1) {
            float ov = __shfl_down_sync(0xffffffff, bv, off);
            int   oi = __shfl_down_sync(0xffffffff, bi, off);
            if (ov > bv || (ov == bv && oi < bi)) { bv = ov; bi = oi; }
        }
        if (lane == 0) amax[r] = (float)bi;
        __syncwarp();
    }
}

// ---------------- launch ----------------
extern "C" void kernel_launch(void* const* d_in, const int* in_sizes, int n_in,
                              void* d_out, int out_size)
{
    const float* x      = (const float*)d_in[0];
    const int*   ei     = (const int*)d_in[1];
    const float* Ws     = (const float*)d_in[2];
    // d_in[3] = bs: per-column constants, cancel exactly under training-mode BN
    const float* gammas = (const float*)d_in[4];
    const float* betas  = (const float*)d_in[5];
    const float* pa     = (const float*)d_in[6];
    const float* Wh1    = (const float*)d_in[7];
    const float* bh1    = (const float*)d_in[8];
    const float* Wh2    = (const float*)d_in[9];
    const float* bh2    = (const float*)d_in[10];
    float* out = (float*)d_out;

    int E = in_sizes[1] / 2;
    const int* srcp = ei;
    const int* dstp = ei + E;

    const int GEMM_SMEM = 98304;   // A 32K + B 64K, 2 blocks/SM
    static int smem_set = 0;
    if (!smem_set) {
        cudaFuncSetAttribute(gemm128_k, cudaFuncAttributeMaxDynamicSharedMemorySize, GEMM_SMEM);
        smem_set = 1;
    }

    void *phw, *pagg;
    cudaGetSymbolAddress(&phw,  g_hw4);
    cudaGetSymbolAddress(&pagg, g_agg4);
    float4* hw  = (float4*)phw;
    float4* agg = (float4*)pagg;

    int nblk_gemm = (NN + 63) / 64;   // 1563

    // graph prep (g_degi zeroed by previous replay's scanA; globals start zeroed)
    deg_count_k<<<(E + 255) / 256, 256>>>(dstp, E);          // 1
    scanA_k<<<NBLK_SCAN, 256>>>();                           // 2
    scanB_k<<<1, 512>>>();                                   // 3

    // DIAGNOSTIC: csr_agg in the profiled slot (4). Runs on stale-but-bounded
    // state (prev replay's hw/rowptr; zeros on first run). Everything it writes
    // (g_agg, stats[0]) is overwritten/re-zeroed before any consumer reads:
    // gemm0 (zstat=0) zeroes stats[0]; real agg0 rewrites g_agg for all nodes.
    csr_agg_k<<<2368, 256>>>(hw, agg, 0);                    // 4  <- profiled

    // layer-0 GEMM (independent of graph prep)
    gemm128_k<<<nblk_gemm, 256, GEMM_SMEM>>>((const float4*)x, Ws, nullptr, (float*)hw,
                                             NN, -1, 0, 0, gammas, betas, pa, nullptr);  // 5

    scanC_k<<<NBLK_SCAN, 256>>>();                           // 6
    fill_k<<<(E + 255) / 256, 256>>>(srcp, dstp, E);         // 7
    pad_k<<<(NN + 255) / 256, 256>>>();                      // 8

    csr_agg_k<<<2368, 256>>>(hw, agg, 0);                    // 9 (real agg0)

    // layers 1,2: BN(l-1)+PReLU fused into A load; zero stats[l] for upcoming agg
    for (int l = 1; l < 3; l++) {
        gemm128_k<<<nblk_gemm, 256, GEMM_SMEM>>>(agg, Ws + (size_t)l * DD * DD, nullptr,
                                                 (float*)hw, NN, l - 1, 0, l,
                                                 gammas, betas, pa, nullptr);
        csr_agg_k<<<2368, 256>>>(hw, agg, l);
    }

    // head gemm: BN(2)+PReLU on A load (streams embeddings to out), +bh1, relu
    gemm128_k<<<nblk_gemm, 256, GEMM_SMEM>>>(agg, Wh1, bh1, (float*)hw,
                                             NN, 2, 1, -1, gammas, betas, pa, (float4*)out);
    // logits + argmax
    head2_k<<<592, 256>>>(hw, Wh2, bh2,
                          out + (size_t)NN * DD,
                          out + (size_t)NN * (DD + CC));
}

// round 15
// speedup vs baseline: 140.7049x; 140.7049x over previous
#include <cuda_runtime.h>
#include <math.h>

#define NN 100000
#define DD 128
#define CC 40
#define EPSBN 1e-5f
#define EMAX 1000000   // 600000 edges + <=3 pad per node
#define NBLK_SCAN 391  // 391*256 >= NN

// ---- scratch (device globals) ----
__device__ float4 g_hw4[NN * 32];     // h @ W (gemm output)
__device__ float4 g_agg4[NN * 32];    // aggregated
__device__ float  g_dinv[NN];
__device__ int    g_degi[NN];         // zeroed at end of each replay (scanA)
__device__ int    g_rowptr[NN + 1];   // padded-CSR row starts (multiples of 4)
__device__ int    g_cursor[NN];
__device__ int    g_csrsrc[EMAX];
__device__ float  g_csrw[EMAX];
__device__ float  g_stats[3][256];    // per layer: [0:128)=colsum, [128:256)=colsumsq
__device__ int    g_bsum[NBLK_SCAN];
__device__ int    g_boff[NBLK_SCAN];

#define FMA2(acc, a, b) \
    asm("fma.rn.f32x2 %0, %1, %2, %0;" : "+l"(acc) : "l"(a), "l"(b))

// ---------------- degree count ----------------
__global__ void deg_count_k(const int* __restrict__ dst, int E) {
    int e = blockIdx.x * blockDim.x + threadIdx.x;
    if (e < E) atomicAdd(&g_degi[dst[e]], 1);
}

// ---------------- hierarchical scan over padded degrees ----------------
__global__ __launch_bounds__(256) void scanA_k() {
    __shared__ int sm[256];
    int t = threadIdx.x;
    int i = blockIdx.x * 256 + t;
    int d = 0;
    if (i < NN) {
        d = g_degi[i];
        g_degi[i] = 0;                         // ready for next replay
        g_dinv[i] = rsqrtf((float)(d + 1));    // +1 = self-loop
    }
    int p = (d + 3) & ~3;
    sm[t] = p;
    __syncthreads();
#pragma unroll
    for (int off = 1; off < 256; off <<= 1) {
        int v = (t >= off) ? sm[t - off] : 0;
        __syncthreads();
        sm[t] += v;
        __syncthreads();
    }
    if (i < NN) g_rowptr[i] = sm[t] - p;       // exclusive within block
    if (t == 255) g_bsum[blockIdx.x] = sm[255];
}

__global__ void scanB_k() {
    __shared__ int sm[512];
    int t = threadIdx.x;
    int v = (t < NBLK_SCAN) ? g_bsum[t] : 0;
    sm[t] = v;
    __syncthreads();
#pragma unroll
    for (int off = 1; off < 512; off <<= 1) {
        int u = (t >= off) ? sm[t - off] : 0;
        __syncthreads();
        sm[t] += u;
        __syncthreads();
    }
    if (t < NBLK_SCAN) g_boff[t] = sm[t] - v;
    if (t == NBLK_SCAN - 1) g_rowptr[NN] = sm[t];
}

__global__ __launch_bounds__(256) void scanC_k() {
    int i = blockIdx.x * 256 + threadIdx.x;
    if (i >= NN) return;
    int v = g_rowptr[i] + g_boff[blockIdx.x];
    g_rowptr[i] = v;
    g_cursor[i] = v;
}

__global__ void fill_k(const int* __restrict__ src, const int* __restrict__ dst, int E) {
    int e = blockIdx.x * blockDim.x + threadIdx.x;
    if (e >= E) return;
    int s = src[e], d = dst[e];
    int pos = atomicAdd(&g_cursor[d], 1);
    g_csrsrc[pos] = s;
    g_csrw[pos] = g_dinv[s] * g_dinv[d];
}

__global__ void pad_k() {
    int i = blockIdx.x * blockDim.x + threadIdx.x;
    if (i >= NN) return;
    int j = g_cursor[i], end = g_rowptr[i + 1];
    for (; j < end; j++) { g_csrsrc[j] = i; g_csrw[j] = 0.f; }
}

// ---------------- fused GEMM: 64x128 tile, 256 thr, 4x8 microtile, 2 blocks/SM ----------------
// (identical to the 627us R9 build)
__global__ __launch_bounds__(256, 2) void gemm128_k(
    const float4* __restrict__ A4, const float* __restrict__ B,
    const float* __restrict__ bias, float* __restrict__ Cout,
    int n, int bnl, int relu, int zstat,
    const float* __restrict__ gammas, const float* __restrict__ betas,
    const float* __restrict__ pa, float4* __restrict__ hout4)
{
    extern __shared__ float smf[];
    float4* As4 = (float4*)smf;                 // [64 rows][32 chunks] = 32KB
    float4* Bs4 = (float4*)(smf + 64 * DD);     // [128 k][32 chunks] = 64KB
    __shared__ float s_scale[DD];
    __shared__ float s_shift[DD];
    int tid = threadIdx.x;
    int r0 = blockIdx.x * 64;

    if (zstat >= 0) ((float*)g_stats)[zstat * 256 + tid] = 0.f;

    float slope = 0.f;
    if (bnl >= 0) {
        slope = __ldg(&pa[bnl]);
        if (tid < DD) {
            float su = g_stats[bnl][tid];
            float sq = g_stats[bnl][tid + 128];
            const float invN = 1.0f / NN;
            float mu = su * invN;
            float var = sq * invN - mu * mu;
            float rs = rsqrtf(var + EPSBN);
            float g = __ldg(&gammas[bnl * DD + tid]);
            float sc = rs * g;
            s_scale[tid] = sc;
            s_shift[tid] = __ldg(&betas[bnl * DD + tid]) - mu * sc;
        }
    }

    // load B: 4096 float4 / 256 thr = 16 each
    {
        const float4* B4 = (const float4*)B;
#pragma unroll
        for (int i = 0; i < 16; i++) Bs4[tid + i * 256] = B4[tid + i * 256];
    }
    if (bnl >= 0) __syncthreads();   // s_scale ready before A transform

    // load + transform A tile: 2048 float4 / 256 thr = 8 each
#pragma unroll
    for (int i = 0; i < 8; i++) {
        int j = tid + i * 256;
        int r = j >> 5, c4 = j & 31;
        float4 v = make_float4(0.f, 0.f, 0.f, 0.f);
        if (r0 + r < n) {
            v = A4[(size_t)(r0 + r) * 32 + c4];
            if (bnl >= 0) {
                float4 sc = ((const float4*)s_scale)[c4];
                float4 sh = ((const float4*)s_shift)[c4];
                float h;
                h = v.x * sc.x + sh.x;  v.x = h > 0.f ? h : slope * h;
                h = v.y * sc.y + sh.y;  v.y = h > 0.f ? h : slope * h;
                h = v.z * sc.z + sh.z;  v.z = h > 0.f ? h : slope * h;
                h = v.w * sc.w + sh.w;  v.w = h > 0.f ? h : slope * h;
            }
            if (hout4) hout4[(size_t)(r0 + r) * 32 + c4] = v;
        }
        As4[j] = v;
    }
    __syncthreads();

    int ty = tid >> 4;      // 0..15 -> rows ty*4 .. ty*4+3
    int tx = tid & 15;      // chunk tx and chunk tx+16

    const ulonglong2* Bu = (const ulonglong2*)Bs4;

    unsigned long long acc[4][4];
#pragma unroll
    for (int i = 0; i < 4; i++)
#pragma unroll
        for (int j = 0; j < 4; j++) acc[i][j] = 0ULL;

#pragma unroll 2
    for (int k0 = 0; k0 < DD; k0 += 4) {
        float4 a4[4];
#pragma unroll
        for (int i = 0; i < 4; i++)
            a4[i] = As4[(ty * 4 + i) * 32 + (k0 >> 2)];
#pragma unroll
        for (int kk = 0; kk < 4; kk++) {
            ulonglong2 b0 = Bu[(k0 + kk) * 32 + tx];
            ulonglong2 b1 = Bu[(k0 + kk) * 32 + 16 + tx];
#pragma unroll
            for (int i = 0; i < 4; i++) {
                float av = ((const float*)&a4[i])[kk];
                unsigned long long ap;
                asm("mov.b64 %0, {%1, %1};" : "=l"(ap) : "f"(av));
                FMA2(acc[i][0], ap, b0.x);
                FMA2(acc[i][1], ap, b0.y);
                FMA2(acc[i][2], ap, b1.x);
                FMA2(acc[i][3], ap, b1.y);
            }
        }
    }

    float bias0[4], bias1[4];
#pragma unroll
    for (int j = 0; j < 4; j++) {
        bias0[j] = bias ? __ldg(&bias[tx * 4 + j]) : 0.f;
        bias1[j] = bias ? __ldg(&bias[64 + tx * 4 + j]) : 0.f;
    }

#pragma unroll
    for (int i = 0; i < 4; i++) {
        int r = r0 + ty * 4 + i;
        if (r < n) {
            float c0, c1, c2, c3, c4f, c5, c6, c7;
            asm("mov.b64 {%0, %1}, %2;" : "=f"(c0), "=f"(c1) : "l"(acc[i][0]));
            asm("mov.b64 {%0, %1}, %2;" : "=f"(c2), "=f"(c3) : "l"(acc[i][1]));
            asm("mov.b64 {%0, %1}, %2;" : "=f"(c4f), "=f"(c5) : "l"(acc[i][2]));
            asm("mov.b64 {%0, %1}, %2;" : "=f"(c6), "=f"(c7) : "l"(acc[i][3]));
            float4 o0 = make_float4(c0 + bias0[0], c1 + bias0[1], c2 + bias0[2], c3 + bias0[3]);
            float4 o1 = make_float4(c4f + bias1[0], c5 + bias1[1], c6 + bias1[2], c7 + bias1[3]);
            if (relu) {
                o0.x = fmaxf(o0.x, 0.f); o0.y = fmaxf(o0.y, 0.f);
                o0.z = fmaxf(o0.z, 0.f); o0.w = fmaxf(o0.w, 0.f);
                o1.x = fmaxf(o1.x, 0.f); o1.y = fmaxf(o1.y, 0.f);
                o1.z = fmaxf(o1.z, 0.f); o1.w = fmaxf(o1.w, 0.f);
            }
            float4* Cr = (float4*)(Cout + (size_t)r * DD);
            Cr[tx]      = o0;
            Cr[16 + tx] = o1;
        }
    }
}

// ---------------- CSR aggregation: meta + FIRST-CHUNK index prefetch + BN stats ----------------
__global__ __launch_bounds__(256) void csr_agg_k(const float4* __restrict__ hw,
                                                 float4* __restrict__ agg, int l)
{
    __shared__ float s_part[8][256];
    int tid = threadIdx.x, w = tid >> 5, lane = tid & 31;
    float4 rs = make_float4(0.f, 0.f, 0.f, 0.f);
    float4 rq = make_float4(0.f, 0.f, 0.f, 0.f);
    int nw = gridDim.x * 8;
    int i = blockIdx.x * 8 + w;

    // prefetch first node's metadata + first index chunk
    int rp0 = 0, rp1 = 0;
    float di = 0.f;
    int4   ps = make_int4(0, 0, 0, 0);
    float4 pw = make_float4(0.f, 0.f, 0.f, 0.f);
    if (i < NN) {
        rp0 = g_rowptr[i];
        rp1 = g_rowptr[i + 1];
        di  = g_dinv[i];
        if (rp1 > rp0) {
            ps = *(const int4*)(g_csrsrc + rp0);
            pw = *(const float4*)(g_csrw + rp0);
        }
    }

    while (i < NN) {
        int inext = i + nw;
        int np0 = 0, np1 = 0;
        float ndi = 0.f;
        int4   ns = make_int4(0, 0, 0, 0);
        float4 nwt = make_float4(0.f, 0.f, 0.f, 0.f);
        if (inext < NN) {            // prefetch next node's meta + first chunk
            np0 = g_rowptr[inext];
            np1 = g_rowptr[inext + 1];
            ndi = g_dinv[inext];
            if (np1 > np0) {
                ns  = *(const int4*)(g_csrsrc + np0);
                nwt = *(const float4*)(g_csrw + np0);
            }
        }

        float sw = di * di;
        float4 v = hw[(size_t)i * 32 + lane];
        v.x *= sw; v.y *= sw; v.z *= sw; v.w *= sw;

        if (rp1 > rp0) {
            // first 4-chunk: indices already in registers -> gathers issue immediately
            {
                float4 u0 = hw[(size_t)ps.x * 32 + lane];
                float4 u1 = hw[(size_t)ps.y * 32 + lane];
                float4 u2 = hw[(size_t)ps.z * 32 + lane];
                float4 u3 = hw[(size_t)ps.w * 32 + lane];
                v.x += pw.x * u0.x + pw.y * u1.x + pw.z * u2.x + pw.w * u3.x;
                v.y += pw.x * u0.y + pw.y * u1.y + pw.z * u2.y + pw.w * u3.y;
                v.z += pw.x * u0.z + pw.y * u1.z + pw.z * u2.z + pw.w * u3.z;
                v.w += pw.x * u0.w + pw.y * u1.w + pw.z * u2.w + pw.w * u3.w;
            }
            int j = rp0 + 4, end = rp1;
            for (; j + 8 <= end; j += 8) {
                int4   sa = *(const int4*)(g_csrsrc + j);
                int4   sb = *(const int4*)(g_csrsrc + j + 4);
                float4 wa = *(const float4*)(g_csrw + j);
                float4 wb = *(const float4*)(g_csrw + j + 4);
                float4 u0 = hw[(size_t)sa.x * 32 + lane];
                float4 u1 = hw[(size_t)sa.y * 32 + lane];
                float4 u2 = hw[(size_t)sa.z * 32 + lane];
                float4 u3 = hw[(size_t)sa.w * 32 + lane];
                float4 u4 = hw[(size_t)sb.x * 32 + lane];
                float4 u5 = hw[(size_t)sb.y * 32 + lane];
                float4 u6 = hw[(size_t)sb.z * 32 + lane];
                float4 u7 = hw[(size_t)sb.w * 32 + lane];
                v.x += wa.x * u0.x + wa.y * u1.x + wa.z * u2.x + wa.w * u3.x
                     + wb.x * u4.x + wb.y * u5.x + wb.z * u6.x + wb.w * u7.x;
                v.y += wa.x * u0.y + wa.y * u1.y + wa.z * u2.y + wa.w * u3.y
                     + wb.x * u4.y + wb.y * u5.y + wb.z * u6.y + wb.w * u7.y;
                v.z += wa.x * u0.z + wa.y * u1.z + wa.z * u2.z + wa.w * u3.z
                     + wb.x * u4.z + wb.y * u5.z + wb.z * u6.z + wb.w * u7.z;
                v.w += wa.x * u0.w + wa.y * u1.w + wa.z * u2.w + wa.w * u3.w
                     + wb.x * u4.w + wb.y * u5.w + wb.z * u6.w + wb.w * u7.w;
            }
            if (j < end) {
                int4   s4 = *(const int4*)(g_csrsrc + j);
                float4 w4 = *(const float4*)(g_csrw + j);
                float4 u0 = hw[(size_t)s4.x * 32 + lane];
                float4 u1 = hw[(size_t)s4.y * 32 + lane];
                float4 u2 = hw[(size_t)s4.z * 32 + lane];
                float4 u3 = hw[(size_t)s4.w * 32 + lane];
                v.x += w4.x * u0.x + w4.y * u1.x + w4.z * u2.x + w4.w * u3.x;
                v.y += w4.x * u0.y + w4.y * u1.y + w4.z * u2.y + w4.w * u3.y;
                v.z += w4.x * u0.z + w4.y * u1.z + w4.z * u2.z + w4.w * u3.z;
                v.w += w4.x * u0.w + w4.y * u1.w + w4.z * u2.w + w4.w * u3.w;
            }
        }
        agg[(size_t)i * 32 + lane] = v;
        rs.x += v.x; rs.y += v.y; rs.z += v.z; rs.w += v.w;
        rq.x += v.x * v.x; rq.y += v.y * v.y; rq.z += v.z * v.z; rq.w += v.w * v.w;

        i = inext; rp0 = np0; rp1 = np1; di = ndi; ps = ns; pw = nwt;
    }
    ((float4*)&s_part[w][0])[lane] = rs;
    ((float4*)&s_part[w][128])[lane] = rq;
    __syncthreads();
    float a = 0.f;
#pragma unroll
    for (int w2 = 0; w2 < 8; w2++) a += s_part[w2][tid];
    atomicAdd(&((float*)g_stats)[l * 256 + tid], a);
}

// ---------------- head: logits = T @ Wh2 + bh2, argmax (first-index ties) ----------------
__global__ __launch_bounds__(256) void head2_k(const float4* __restrict__ T4,
                                               const float* __restrict__ Wh2,
                                               const float* __restrict__ bh2,
                                               float* __restrict__ logits,
                                               float* __restrict__ amax)
{
    __shared__ float4 Wt[CC][32];   // [col][chunk], XOR swizzled
    __shared__ float bsh[CC];
    int tid = threadIdx.x;
    for (int idx = tid; idx < CC * 32; idx += 256) {
        int c = idx >> 5, q = idx & 31;
        int k = q * 4;
        float4 v = make_float4(Wh2[k * CC + c], Wh2[(k + 1) * CC + c],
                               Wh2[(k + 2) * CC + c], Wh2[(k + 3) * CC + c]);
        Wt[c][q ^ (c & 31)] = v;
    }
    if (tid < CC) bsh[tid] = bh2[tid];
    __syncthreads();

    int w = tid >> 5, lane = tid & 31;
    __shared__ float4 rows[8][32];
    for (int r = blockIdx.x * 8 + w; r < NN; r += gridDim.x * 8) {
        rows[w][lane] = T4[(size_t)r * 32 + lane];
        __syncwarp();

        bool has2 = lane < 8;
        float acc0 = bsh[lane];
        float acc1 = has2 ? bsh[32 + lane] : -1e30f;
#pragma unroll 8
        for (int q = 0; q < 32; q++) {
            float4 rv = rows[w][q];
            float4 w0 = Wt[lane][q ^ lane];
            acc0 += rv.x * w0.x + rv.y * w0.y + rv.z * w0.z + rv.w * w0.w;
            if (has2) {
                float4 w1 = Wt[32 + lane][q ^ lane];
                acc1 += rv.x * w1.x + rv.y * w1.y + rv.z * w1.z + rv.w * w1.w;
            }
        }
        logits[(size_t)r * CC + lane] = acc0;
        if (has2) logits[(size_t)r * CC + 32 + lane] = acc1;

        float bv = acc0; int bi = lane;
        if (has2 && acc1 > bv) { bv = acc1; bi = 32 + lane; }
#pragma unroll
        for (int off = 16; off > 0; off >>= 1) {
            float ov = __shfl_down_sync(0xffffffff, bv, off);
            int   oi = __shfl_down_sync(0xffffffff, bi, off);
            if (ov > bv || (ov == bv && oi < bi)) { bv = ov; bi = oi; }
        }
        if (lane == 0) amax[r] = (float)bi;
        __syncwarp();
    }
}

// ---------------- launch ----------------
extern "C" void kernel_launch(void* const* d_in, const int* in_sizes, int n_in,
                              void* d_out, int out_size)
{
    const float* x      = (const float*)d_in[0];
    const int*   ei     = (const int*)d_in[1];
    const float* Ws     = (const float*)d_in[2];
    // d_in[3] = bs: per-column constants, cancel exactly under training-mode BN
    const float* gammas = (const float*)d_in[4];
    const float* betas  = (const float*)d_in[5];
    const float* pa     = (const float*)d_in[6];
    const float* Wh1    = (const float*)d_in[7];
    const float* bh1    = (const float*)d_in[8];
    const float* Wh2    = (const float*)d_in[9];
    const float* bh2    = (const float*)d_in[10];
    float* out = (float*)d_out;

    int E = in_sizes[1] / 2;
    const int* srcp = ei;
    const int* dstp = ei + E;

    const int GEMM_SMEM = 98304;   // A 32K + B 64K, 2 blocks/SM
    static int smem_set = 0;
    if (!smem_set) {
        cudaFuncSetAttribute(gemm128_k, cudaFuncAttributeMaxDynamicSharedMemorySize, GEMM_SMEM);
        smem_set = 1;
    }

    void *phw, *pagg;
    cudaGetSymbolAddress(&phw,  g_hw4);
    cudaGetSymbolAddress(&pagg, g_agg4);
    float4* hw  = (float4*)phw;
    float4* agg = (float4*)pagg;

    int nblk_gemm = (NN + 63) / 64;   // 1563

    // graph prep (g_degi zeroed by previous replay's scanA; globals start zeroed)
    deg_count_k<<<(E + 255) / 256, 256>>>(dstp, E);          // 1
    scanA_k<<<NBLK_SCAN, 256>>>();                           // 2
    scanB_k<<<1, 512>>>();                                   // 3

    // layer-0 GEMM (independent of graph prep) -- slot 4, gets profiled
    gemm128_k<<<nblk_gemm, 256, GEMM_SMEM>>>((const float4*)x, Ws, nullptr, (float*)hw,
                                             NN, -1, 0, 0, gammas, betas, pa, nullptr);  // 4

    scanC_k<<<NBLK_SCAN, 256>>>();                           // 5
    fill_k<<<(E + 255) / 256, 256>>>(srcp, dstp, E);         // 6
    pad_k<<<(NN + 255) / 256, 256>>>();                      // 7

    csr_agg_k<<<2368, 256>>>(hw, agg, 0);                    // 8

    // layers 1,2: BN(l-1)+PReLU fused into A load; zero stats[l] for upcoming agg
    for (int l = 1; l < 3; l++) {
        gemm128_k<<<nblk_gemm, 256, GEMM_SMEM>>>(agg, Ws + (size_t)l * DD * DD, nullptr,
                                                 (float*)hw, NN, l - 1, 0, l,
                                                 gammas, betas, pa, nullptr);
        csr_agg_k<<<2368, 256>>>(hw, agg, l);
    }

    // head gemm: BN(2)+PReLU on A load (streams embeddings to out), +bh1, relu
    gemm128_k<<<nblk_gemm, 256, GEMM_SMEM>>>(agg, Wh1, bh1, (float*)hw,
                                             NN, 2, 1, -1, gammas, betas, pa, (float4*)out);
    // logits + argmax
    head2_k<<<592, 256>>>(hw, Wh2, bh2,
                          out + (size_t)NN * DD,
                          out + (size_t)NN * (DD + CC));
}

// round 16
// speedup vs baseline: 142.5170x; 1.0129x over previous
#include <cuda_runtime.h>
#include <math.h>

#define NN 100000
#define DD 128
#define CC 40
#define EPSBN 1e-5f
#define EMAX 1000000   // 600000 edges + <=3 pad per node
#define NBLK_SCAN 391  // 391*256 >= NN

// ---- scratch (device globals) ----
__device__ float4 g_hw4[NN * 32];     // h @ W (gemm output)
__device__ float4 g_agg4[NN * 32];    // aggregated
__device__ float  g_dinv[NN];
__device__ int    g_degi[NN];         // zeroed at end of each replay (scanA)
__device__ int    g_rowptr[NN + 1];   // padded-CSR row starts (multiples of 4)
__device__ int    g_cursor[NN];
__device__ int    g_csrsrc[EMAX];
__device__ float  g_csrw[EMAX];
__device__ float  g_stats[3][256];    // per layer: [0:128)=colsum, [128:256)=colsumsq
__device__ int    g_bsum[NBLK_SCAN];
__device__ int    g_boff[NBLK_SCAN];

#define FMA2(acc, a, b) \
    asm("fma.rn.f32x2 %0, %1, %2, %0;" : "+l"(acc) : "l"(a), "l"(b))

// ---------------- degree count ----------------
__global__ void deg_count_k(const int* __restrict__ dst, int E) {
    int e = blockIdx.x * blockDim.x + threadIdx.x;
    if (e < E) atomicAdd(&g_degi[dst[e]], 1);
}

// ---------------- hierarchical scan over padded degrees ----------------
__global__ __launch_bounds__(256) void scanA_k() {
    __shared__ int sm[256];
    int t = threadIdx.x;
    int i = blockIdx.x * 256 + t;
    int d = 0;
    if (i < NN) {
        d = g_degi[i];
        g_degi[i] = 0;                         // ready for next replay
        g_dinv[i] = rsqrtf((float)(d + 1));    // +1 = self-loop
    }
    int p = (d + 3) & ~3;
    sm[t] = p;
    __syncthreads();
#pragma unroll
    for (int off = 1; off < 256; off <<= 1) {
        int v = (t >= off) ? sm[t - off] : 0;
        __syncthreads();
        sm[t] += v;
        __syncthreads();
    }
    if (i < NN) g_rowptr[i] = sm[t] - p;       // exclusive within block
    if (t == 255) g_bsum[blockIdx.x] = sm[255];
}

__global__ void scanB_k() {
    __shared__ int sm[512];
    int t = threadIdx.x;
    int v = (t < NBLK_SCAN) ? g_bsum[t] : 0;
    sm[t] = v;
    __syncthreads();
#pragma unroll
    for (int off = 1; off < 512; off <<= 1) {
        int u = (t >= off) ? sm[t - off] : 0;
        __syncthreads();
        sm[t] += u;
        __syncthreads();
    }
    if (t < NBLK_SCAN) g_boff[t] = sm[t] - v;
    if (t == NBLK_SCAN - 1) g_rowptr[NN] = sm[t];
}

__global__ __launch_bounds__(256) void scanC_k() {
    int i = blockIdx.x * 256 + threadIdx.x;
    if (i >= NN) return;
    int v = g_rowptr[i] + g_boff[blockIdx.x];
    g_rowptr[i] = v;
    g_cursor[i] = v;
}

__global__ void fill_k(const int* __restrict__ src, const int* __restrict__ dst, int E) {
    int e = blockIdx.x * blockDim.x + threadIdx.x;
    if (e >= E) return;
    int s = src[e], d = dst[e];
    int pos = atomicAdd(&g_cursor[d], 1);
    g_csrsrc[pos] = s;
    g_csrw[pos] = g_dinv[s] * g_dinv[d];
}

__global__ void pad_k() {
    int i = blockIdx.x * blockDim.x + threadIdx.x;
    if (i >= NN) return;
    int j = g_cursor[i], end = g_rowptr[i + 1];
    for (; j < end; j++) { g_csrsrc[j] = i; g_csrw[j] = 0.f; }
}

// ---------------- fused GEMM: 64x128 tile, 256 thr, 4x8 microtile, 2 blocks/SM ----------------
// (identical to the 627us R9 build)
__global__ __launch_bounds__(256, 2) void gemm128_k(
    const float4* __restrict__ A4, const float* __restrict__ B,
    const float* __restrict__ bias, float* __restrict__ Cout,
    int n, int bnl, int relu, int zstat,
    const float* __restrict__ gammas, const float* __restrict__ betas,
    const float* __restrict__ pa, float4* __restrict__ hout4)
{
    extern __shared__ float smf[];
    float4* As4 = (float4*)smf;                 // [64 rows][32 chunks] = 32KB
    float4* Bs4 = (float4*)(smf + 64 * DD);     // [128 k][32 chunks] = 64KB
    __shared__ float s_scale[DD];
    __shared__ float s_shift[DD];
    int tid = threadIdx.x;
    int r0 = blockIdx.x * 64;

    if (zstat >= 0) ((float*)g_stats)[zstat * 256 + tid] = 0.f;

    float slope = 0.f;
    if (bnl >= 0) {
        slope = __ldg(&pa[bnl]);
        if (tid < DD) {
            float su = g_stats[bnl][tid];
            float sq = g_stats[bnl][tid + 128];
            const float invN = 1.0f / NN;
            float mu = su * invN;
            float var = sq * invN - mu * mu;
            float rs = rsqrtf(var + EPSBN);
            float g = __ldg(&gammas[bnl * DD + tid]);
            float sc = rs * g;
            s_scale[tid] = sc;
            s_shift[tid] = __ldg(&betas[bnl * DD + tid]) - mu * sc;
        }
    }

    // load B: 4096 float4 / 256 thr = 16 each
    {
        const float4* B4 = (const float4*)B;
#pragma unroll
        for (int i = 0; i < 16; i++) Bs4[tid + i * 256] = B4[tid + i * 256];
    }
    if (bnl >= 0) __syncthreads();   // s_scale ready before A transform

    // load + transform A tile: 2048 float4 / 256 thr = 8 each
#pragma unroll
    for (int i = 0; i < 8; i++) {
        int j = tid + i * 256;
        int r = j >> 5, c4 = j & 31;
        float4 v = make_float4(0.f, 0.f, 0.f, 0.f);
        if (r0 + r < n) {
            v = A4[(size_t)(r0 + r) * 32 + c4];
            if (bnl >= 0) {
                float4 sc = ((const float4*)s_scale)[c4];
                float4 sh = ((const float4*)s_shift)[c4];
                float h;
                h = v.x * sc.x + sh.x;  v.x = h > 0.f ? h : slope * h;
                h = v.y * sc.y + sh.y;  v.y = h > 0.f ? h : slope * h;
                h = v.z * sc.z + sh.z;  v.z = h > 0.f ? h : slope * h;
                h = v.w * sc.w + sh.w;  v.w = h > 0.f ? h : slope * h;
            }
            if (hout4) hout4[(size_t)(r0 + r) * 32 + c4] = v;
        }
        As4[j] = v;
    }
    __syncthreads();

    int ty = tid >> 4;      // 0..15 -> rows ty*4 .. ty*4+3
    int tx = tid & 15;      // chunk tx and chunk tx+16

    const ulonglong2* Bu = (const ulonglong2*)Bs4;

    unsigned long long acc[4][4];
#pragma unroll
    for (int i = 0; i < 4; i++)
#pragma unroll
        for (int j = 0; j < 4; j++) acc[i][j] = 0ULL;

#pragma unroll 2
    for (int k0 = 0; k0 < DD; k0 += 4) {
        float4 a4[4];
#pragma unroll
        for (int i = 0; i < 4; i++)
            a4[i] = As4[(ty * 4 + i) * 32 + (k0 >> 2)];
#pragma unroll
        for (int kk = 0; kk < 4; kk++) {
            ulonglong2 b0 = Bu[(k0 + kk) * 32 + tx];
            ulonglong2 b1 = Bu[(k0 + kk) * 32 + 16 + tx];
#pragma unroll
            for (int i = 0; i < 4; i++) {
                float av = ((const float*)&a4[i])[kk];
                unsigned long long ap;
                asm("mov.b64 %0, {%1, %1};" : "=l"(ap) : "f"(av));
                FMA2(acc[i][0], ap, b0.x);
                FMA2(acc[i][1], ap, b0.y);
                FMA2(acc[i][2], ap, b1.x);
                FMA2(acc[i][3], ap, b1.y);
            }
        }
    }

    float bias0[4], bias1[4];
#pragma unroll
    for (int j = 0; j < 4; j++) {
        bias0[j] = bias ? __ldg(&bias[tx * 4 + j]) : 0.f;
        bias1[j] = bias ? __ldg(&bias[64 + tx * 4 + j]) : 0.f;
    }

#pragma unroll
    for (int i = 0; i < 4; i++) {
        int r = r0 + ty * 4 + i;
        if (r < n) {
            float c0, c1, c2, c3, c4f, c5, c6, c7;
            asm("mov.b64 {%0, %1}, %2;" : "=f"(c0), "=f"(c1) : "l"(acc[i][0]));
            asm("mov.b64 {%0, %1}, %2;" : "=f"(c2), "=f"(c3) : "l"(acc[i][1]));
            asm("mov.b64 {%0, %1}, %2;" : "=f"(c4f), "=f"(c5) : "l"(acc[i][2]));
            asm("mov.b64 {%0, %1}, %2;" : "=f"(c6), "=f"(c7) : "l"(acc[i][3]));
            float4 o0 = make_float4(c0 + bias0[0], c1 + bias0[1], c2 + bias0[2], c3 + bias0[3]);
            float4 o1 = make_float4(c4f + bias1[0], c5 + bias1[1], c6 + bias1[2], c7 + bias1[3]);
            if (relu) {
                o0.x = fmaxf(o0.x, 0.f); o0.y = fmaxf(o0.y, 0.f);
                o0.z = fmaxf(o0.z, 0.f); o0.w = fmaxf(o0.w, 0.f);
                o1.x = fmaxf(o1.x, 0.f); o1.y = fmaxf(o1.y, 0.f);
                o1.z = fmaxf(o1.z, 0.f); o1.w = fmaxf(o1.w, 0.f);
            }
            float4* Cr = (float4*)(Cout + (size_t)r * DD);
            Cr[tx]      = o0;
            Cr[16 + tx] = o1;
        }
    }
}

// ---------------- CSR aggregation: TWO nodes per warp, interleaved + BN stats ----------------
__global__ __launch_bounds__(256) void csr_agg_k(const float4* __restrict__ hw,
                                                 float4* __restrict__ agg, int l)
{
    __shared__ float s_part[8][256];
    int tid = threadIdx.x, w = tid >> 5, lane = tid & 31;
    float4 rs = make_float4(0.f, 0.f, 0.f, 0.f);
    float4 rq = make_float4(0.f, 0.f, 0.f, 0.f);
    int nw = gridDim.x * 8;
    int base = blockIdx.x * 8 + w;

    for (int i0 = base; i0 < NN; i0 += 2 * nw) {
        int i1 = i0 + nw;
        bool h1 = i1 < NN;

        // both nodes' metadata in flight together
        int ea, eb = 0, ja, jb = 0;
        float d0, d1 = 0.f;
        ja = g_rowptr[i0];
        if (h1) jb = g_rowptr[i1];
        ea = g_rowptr[i0 + 1];
        if (h1) eb = g_rowptr[i1 + 1];
        d0 = g_dinv[i0];
        if (h1) d1 = g_dinv[i1];

        // both self-loop rows in flight together
        float4 v0 = hw[(size_t)i0 * 32 + lane];
        float4 v1 = h1 ? hw[(size_t)i1 * 32 + lane] : make_float4(0.f, 0.f, 0.f, 0.f);
        float sw0 = d0 * d0, sw1 = d1 * d1;
        v0.x *= sw0; v0.y *= sw0; v0.z *= sw0; v0.w *= sw0;
        v1.x *= sw1; v1.y *= sw1; v1.z *= sw1; v1.w *= sw1;

        // interleaved chunk loop: 4 gathers per live node per iteration (MLP up to 8)
        while (ja < ea || jb < eb) {
            bool da = ja < ea, db = jb < eb;
            int4 sa, sb;
            float4 wa, wb;
            if (da) { sa = *(const int4*)(g_csrsrc + ja); wa = *(const float4*)(g_csrw + ja); }
            if (db) { sb = *(const int4*)(g_csrsrc + jb); wb = *(const float4*)(g_csrw + jb); }
            if (da) {
                float4 u0 = hw[(size_t)sa.x * 32 + lane];
                float4 u1 = hw[(size_t)sa.y * 32 + lane];
                float4 u2 = hw[(size_t)sa.z * 32 + lane];
                float4 u3 = hw[(size_t)sa.w * 32 + lane];
                v0.x += wa.x * u0.x + wa.y * u1.x + wa.z * u2.x + wa.w * u3.x;
                v0.y += wa.x * u0.y + wa.y * u1.y + wa.z * u2.y + wa.w * u3.y;
                v0.z += wa.x * u0.z + wa.y * u1.z + wa.z * u2.z + wa.w * u3.z;
                v0.w += wa.x * u0.w + wa.y * u1.w + wa.z * u2.w + wa.w * u3.w;
                ja += 4;
            }
            if (db) {
                float4 u0 = hw[(size_t)sb.x * 32 + lane];
                float4 u1 = hw[(size_t)sb.y * 32 + lane];
                float4 u2 = hw[(size_t)sb.z * 32 + lane];
                float4 u3 = hw[(size_t)sb.w * 32 + lane];
                v1.x += wb.x * u0.x + wb.y * u1.x + wb.z * u2.x + wb.w * u3.x;
                v1.y += wb.x * u0.y + wb.y * u1.y + wb.z * u2.y + wb.w * u3.y;
                v1.z += wb.x * u0.z + wb.y * u1.z + wb.z * u2.z + wb.w * u3.z;
                v1.w += wb.x * u0.w + wb.y * u1.w + wb.z * u2.w + wb.w * u3.w;
                jb += 4;
            }
        }

        agg[(size_t)i0 * 32 + lane] = v0;
        rs.x += v0.x; rs.y += v0.y; rs.z += v0.z; rs.w += v0.w;
        rq.x += v0.x * v0.x; rq.y += v0.y * v0.y; rq.z += v0.z * v0.z; rq.w += v0.w * v0.w;
        if (h1) {
            agg[(size_t)i1 * 32 + lane] = v1;
            rs.x += v1.x; rs.y += v1.y; rs.z += v1.z; rs.w += v1.w;
            rq.x += v1.x * v1.x; rq.y += v1.y * v1.y; rq.z += v1.z * v1.z; rq.w += v1.w * v1.w;
        }
    }
    ((float4*)&s_part[w][0])[lane] = rs;
    ((float4*)&s_part[w][128])[lane] = rq;
    __syncthreads();
    float a = 0.f;
#pragma unroll
    for (int w2 = 0; w2 < 8; w2++) a += s_part[w2][tid];
    atomicAdd(&((float*)g_stats)[l * 256 + tid], a);
}

// ---------------- head: logits = T @ Wh2 + bh2, argmax (first-index ties) ----------------
__global__ __launch_bounds__(256) void head2_k(const float4* __restrict__ T4,
                                               const float* __restrict__ Wh2,
                                               const float* __restrict__ bh2,
                                               float* __restrict__ logits,
                                               float* __restrict__ amax)
{
    __shared__ float4 Wt[CC][32];   // [col][chunk], XOR swizzled
    __shared__ float bsh[CC];
    int tid = threadIdx.x;
    for (int idx = tid; idx < CC * 32; idx += 256) {
        int c = idx >> 5, q = idx & 31;
        int k = q * 4;
        float4 v = make_float4(Wh2[k * CC + c], Wh2[(k + 1) * CC + c],
                               Wh2[(k + 2) * CC + c], Wh2[(k + 3) * CC + c]);
        Wt[c][q ^ (c & 31)] = v;
    }
    if (tid < CC) bsh[tid] = bh2[tid];
    __syncthreads();

    int w = tid >> 5, lane = tid & 31;
    __shared__ float4 rows[8][32];
    for (int r = blockIdx.x * 8 + w; r < NN; r += gridDim.x * 8) {
        rows[w][lane] = T4[(size_t)r * 32 + lane];
        __syncwarp();

        bool has2 = lane < 8;
        float acc0 = bsh[lane];
        float acc1 = has2 ? bsh[32 + lane] : -1e30f;
#pragma unroll 8
        for (int q = 0; q < 32; q++) {
            float4 rv = rows[w][q];
            float4 w0 = Wt[lane][q ^ lane];
            acc0 += rv.x * w0.x + rv.y * w0.y + rv.z * w0.z + rv.w * w0.w;
            if (has2) {
                float4 w1 = Wt[32 + lane][q ^ lane];
                acc1 += rv.x * w1.x + rv.y * w1.y + rv.z * w1.z + rv.w * w1.w;
            }
        }
        logits[(size_t)r * CC + lane] = acc0;
        if (has2) logits[(size_t)r * CC + 32 + lane] = acc1;

        float bv = acc0; int bi = lane;
        if (has2 && acc1 > bv) { bv = acc1; bi = 32 + lane; }
#pragma unroll
        for (int off = 16; off > 0; off >>= 1) {
            float ov = __shfl_down_sync(0xffffffff, bv, off);
            int   oi = __shfl_down_sync(0xffffffff, bi, off);
            if (ov > bv || (ov == bv && oi < bi)) { bv = ov; bi = oi; }
        }
        if (lane == 0) amax[r] = (float)bi;
        __syncwarp();
    }
}

// ---------------- launch ----------------
extern "C" void kernel_launch(void* const* d_in, const int* in_sizes, int n_in,
                              void* d_out, int out_size)
{
    const float* x      = (const float*)d_in[0];
    const int*   ei     = (const int*)d_in[1];
    const float* Ws     = (const float*)d_in[2];
    // d_in[3] = bs: per-column constants, cancel exactly under training-mode BN
    const float* gammas = (const float*)d_in[4];
    const float* betas  = (const float*)d_in[5];
    const float* pa     = (const float*)d_in[6];
    const float* Wh1    = (const float*)d_in[7];
    const float* bh1    = (const float*)d_in[8];
    const float* Wh2    = (const float*)d_in[9];
    const float* bh2    = (const float*)d_in[10];
    float* out = (float*)d_out;

    int E = in_sizes[1] / 2;
    const int* srcp = ei;
    const int* dstp = ei + E;

    const int GEMM_SMEM = 98304;   // A 32K + B 64K, 2 blocks/SM
    static int smem_set = 0;
    if (!smem_set) {
        cudaFuncSetAttribute(gemm128_k, cudaFuncAttributeMaxDynamicSharedMemorySize, GEMM_SMEM);
        smem_set = 1;
    }

    void *phw, *pagg;
    cudaGetSymbolAddress(&phw,  g_hw4);
    cudaGetSymbolAddress(&pagg, g_agg4);
    float4* hw  = (float4*)phw;
    float4* agg = (float4*)pagg;

    int nblk_gemm = (NN + 63) / 64;   // 1563

    // graph prep (g_degi zeroed by previous replay's scanA; globals start zeroed)
    deg_count_k<<<(E + 255) / 256, 256>>>(dstp, E);          // 1
    scanA_k<<<NBLK_SCAN, 256>>>();                           // 2
    scanB_k<<<1, 512>>>();                                   // 3

    // layer-0 GEMM (independent of graph prep) -- slot 4, gets profiled
    gemm128_k<<<nblk_gemm, 256, GEMM_SMEM>>>((const float4*)x, Ws, nullptr, (float*)hw,
                                             NN, -1, 0, 0, gammas, betas, pa, nullptr);  // 4

    scanC_k<<<NBLK_SCAN, 256>>>();                           // 5
    fill_k<<<(E + 255) / 256, 256>>>(srcp, dstp, E);         // 6
    pad_k<<<(NN + 255) / 256, 256>>>();                      // 7

    csr_agg_k<<<2368, 256>>>(hw, agg, 0);                    // 8

    // layers 1,2: BN(l-1)+PReLU fused into A load; zero stats[l] for upcoming agg
    for (int l = 1; l < 3; l++) {
        gemm128_k<<<nblk_gemm, 256, GEMM_SMEM>>>(agg, Ws + (size_t)l * DD * DD, nullptr,
                                                 (float*)hw, NN, l - 1, 0, l,
                                                 gammas, betas, pa, nullptr);
        csr_agg_k<<<2368, 256>>>(hw, agg, l);
    }

    // head gemm: BN(2)+PReLU on A load (streams embeddings to out), +bh1, relu
    gemm128_k<<<nblk_gemm, 256, GEMM_SMEM>>>(agg, Wh1, bh1, (float*)hw,
                                             NN, 2, 1, -1, gammas, betas, pa, (float4*)out);
    // logits + argmax
    head2_k<<<592, 256>>>(hw, Wh2, bh2,
                          out + (size_t)NN * DD,
                          out + (size_t)NN * (DD + CC));
}